// round 9
// baseline (speedup 1.0000x reference)
#include <cuda_runtime.h>
#include <cuda_bf16.h>
#include <cuda_fp16.h>
#include <math.h>
#include <stdint.h>

#define N_NODES 100000
#define N_FEAT  512
#define HIDDEN  128
#define N_CLASS 16
#define N_EDGES 3200000
#define ALPHA   0.25f

// ---------------- scratch (static device globals; no allocation) -------------
__device__ float  g_local[(size_t)N_NODES * N_CLASS];          // fp32 local logits
__device__ __half g_loc16[(size_t)N_NODES * N_CLASS];          // fp16 copy (gather)
__device__ __half g_buf16[(size_t)N_NODES * N_CLASS];          // fp16 iter-1 out
__device__ int    g_deg[N_NODES];
__device__ int    g_rowptr[N_NODES + 1];
__device__ int    g_wptr[N_NODES];
__device__ float  g_scale[N_NODES];
__device__ int    g_csr[N_EDGES];
__device__ __nv_bfloat16 g_w1bt[(size_t)HIDDEN * N_FEAT];      // W1^T bf16 [n][k]
__device__ __nv_bfloat16 g_xb[(size_t)N_NODES * N_FEAT];       // X bf16 [node][k]

// ---------------- PTX helpers ------------------------------------------------
__device__ __forceinline__ uint32_t smem_u32(const void* p) {
    uint32_t a;
    asm("{ .reg .u64 t; cvta.to.shared.u64 t, %1; cvt.u32.u64 %0, t; }" : "=r"(a) : "l"(p));
    return a;
}
__device__ __forceinline__ void cp_async16(uint32_t dst, const void* src, uint32_t srcsize) {
    asm volatile("cp.async.cg.shared.global [%0], [%1], 16, %2;"
                 :: "r"(dst), "l"(src), "r"(srcsize) : "memory");
}
__device__ __forceinline__ void cp_commit() {
    asm volatile("cp.async.commit_group;" ::: "memory");
}
template <int N>
__device__ __forceinline__ void cp_wait() {
    asm volatile("cp.async.wait_group %0;" :: "n"(N) : "memory");
}
__device__ __forceinline__ void ldsm_x4(uint32_t* r, uint32_t addr) {
    asm volatile("ldmatrix.sync.aligned.m8n8.x4.shared.b16 {%0,%1,%2,%3}, [%4];"
                 : "=r"(r[0]), "=r"(r[1]), "=r"(r[2]), "=r"(r[3]) : "r"(addr));
}
__device__ __forceinline__ void mma_bf16(float* d, const uint32_t* a, const uint32_t* b) {
    asm volatile(
        "mma.sync.aligned.m16n8k16.row.col.f32.bf16.bf16.f32 "
        "{%0,%1,%2,%3}, {%4,%5,%6,%7}, {%8,%9}, {%0,%1,%2,%3};"
        : "+f"(d[0]), "+f"(d[1]), "+f"(d[2]), "+f"(d[3])
        : "r"(a[0]), "r"(a[1]), "r"(a[2]), "r"(a[3]), "r"(b[0]), "r"(b[1]));
}

// ---------------- CSR build --------------------------------------------------
__global__ void zero_deg_kernel() {
    for (int i = blockIdx.x * blockDim.x + threadIdx.x; i < N_NODES;
         i += gridDim.x * blockDim.x)
        g_deg[i] = 0;
}

__global__ void count_deg_kernel(const int* __restrict__ src) {
    for (int e = blockIdx.x * blockDim.x + threadIdx.x; e < N_EDGES;
         e += gridDim.x * blockDim.x)
        atomicAdd(&g_deg[src[e]], 1);
}

__global__ void scan_kernel() {
    __shared__ int warpsum[32];
    const int t    = threadIdx.x;
    const int lane = t & 31;
    const int w    = t >> 5;
    const int CH   = (N_NODES + 1023) / 1024;
    const int b    = t * CH;
    const int e    = min(b + CH, N_NODES);
    int s = 0;
    for (int i = b; i < e; i++) s += g_deg[i];

    int incl = s;
#pragma unroll
    for (int off = 1; off < 32; off <<= 1) {
        int v = __shfl_up_sync(0xffffffffu, incl, off);
        if (lane >= off) incl += v;
    }
    if (lane == 31) warpsum[w] = incl;
    __syncthreads();
    if (w == 0) {
        int v = warpsum[lane];
        int iv = v;
#pragma unroll
        for (int off = 1; off < 32; off <<= 1) {
            int u = __shfl_up_sync(0xffffffffu, iv, off);
            if (lane >= off) iv += u;
        }
        warpsum[lane] = iv - v;
    }
    __syncthreads();
    int off = warpsum[w] + (incl - s);
    for (int i = b; i < e; i++) {
        int d = g_deg[i];
        g_rowptr[i] = off;
        g_wptr[i]   = off;
        g_scale[i]  = (1.0f - ALPHA) / fmaxf((float)d, 1e-12f);
        off += d;
    }
    if (t == 1023) g_rowptr[N_NODES] = off;
}

__global__ void scatter_kernel(const int* __restrict__ src, const int* __restrict__ dst) {
    for (int e = blockIdx.x * blockDim.x + threadIdx.x; e < N_EDGES;
         e += gridDim.x * blockDim.x) {
        int s = src[e];
        int p = atomicAdd(&g_wptr[s], 1);
        g_csr[p] = dst[e];
    }
}

// ---------------- X -> bf16 --------------------------------------------------
__global__ __launch_bounds__(256)
void conv_x_kernel(const float* __restrict__ X) {
    const size_t total4 = (size_t)N_NODES * N_FEAT / 4;
    for (size_t i = blockIdx.x * blockDim.x + threadIdx.x; i < total4;
         i += (size_t)gridDim.x * blockDim.x) {
        float4 v = *(const float4*)&X[i * 4];
        uint32_t p0, p1;
        asm("cvt.rn.bf16x2.f32 %0, %1, %2;" : "=r"(p0) : "f"(v.y), "f"(v.x));
        asm("cvt.rn.bf16x2.f32 %0, %1, %2;" : "=r"(p1) : "f"(v.w), "f"(v.z));
        *(uint2*)&g_xb[i * 4] = make_uint2(p0, p1);
    }
}

// ---------------- W1 -> bf16 transpose: g_w1bt[n][k] -------------------------
__global__ void conv_w1_kernel(const float* __restrict__ W1) {
    __shared__ float tile[32][33];
    const int bx = blockIdx.x;
    const int by = blockIdx.y;
    const int x = threadIdx.x, y = threadIdx.y;
#pragma unroll
    for (int i = 0; i < 32; i += 8)
        tile[y + i][x] = W1[(size_t)(by * 32 + y + i) * HIDDEN + bx * 32 + x];
    __syncthreads();
#pragma unroll
    for (int i = 0; i < 32; i += 8)
        g_w1bt[(size_t)(bx * 32 + y + i) * N_FEAT + by * 32 + x] =
            __float2bfloat16(tile[x][y + i]);
}

// ---------------- bf16 ldmatrix GEMM (512 threads, no spills) ----------------
// CTA = 128 x 128, 512 threads = 16 warps (4m x 4n), warp tile 32x32.
// acc = 32 regs/thread -> ~90 regs total, no spill. K chunks of 32, dbl buffer.
// SMEM: A bufs [0,20480), B bufs [20480,40960), stride 80B rows.
// Epilogue Hs fp32 overlays [0,67584) stride 132; W2s at 67584 (8KB).
#define AB_STRIDE 80
#define A_BYTE(b)   ((b) * 10240)
#define B_BYTE(b)   (20480 + (b) * 10240)
#define W2S_BYTE    67584
#define GEMM_SMEM_BYTES (67584 + 8192)

__global__ __launch_bounds__(512)
void gemm_mma_kernel(const float* __restrict__ W2) {
    extern __shared__ char smc[];
    float* smf = (float*)smc;
    const uint32_t smb = smem_u32(smc);

    const int tid  = threadIdx.x;
    const int lane = tid & 31;
    const int wid  = tid >> 5;
    const int wm   = wid & 3;        // m offset wm*32
    const int wn   = wid >> 2;       // n offset wn*32
    const int r0   = blockIdx.x * 128;

    float* W2s = (float*)(smc + W2S_BYTE);
    *(float4*)&W2s[tid * 4] = *(const float4*)&W2[tid * 4];   // 2048 floats

    // tile loads: per chunk each operand is 128 rows x 64B = 512 x 16B
    // 512 threads -> exactly one cp.async16 per operand per thread
    const int t_row = tid >> 2;      // 0..127
    const int t_g   = tid & 3;

    auto load_chunk = [&](int chunk, int buf) {
        const int k0 = chunk * 32;
        int grow = r0 + t_row;
        uint32_t sz = (grow < N_NODES) ? 16u : 0u;
        cp_async16(smb + A_BYTE(buf) + t_row * AB_STRIDE + t_g * 16,
                   &g_xb[(size_t)min(grow, N_NODES - 1) * N_FEAT + k0 + t_g * 8], sz);
        cp_async16(smb + B_BYTE(buf) + t_row * AB_STRIDE + t_g * 16,
                   &g_w1bt[(size_t)t_row * N_FEAT + k0 + t_g * 8], 16u);
        cp_commit();
    };

    float acc[2][4][4];
#pragma unroll
    for (int mi = 0; mi < 2; mi++)
#pragma unroll
        for (int ni = 0; ni < 4; ni++)
#pragma unroll
            for (int c = 0; c < 4; c++) acc[mi][ni][c] = 0.0f;

    const int a_row  = wm * 32 + (lane & 7) + ((lane >> 3) & 1) * 8;
    const int a_koff = (lane >> 4) * 8;
    const int b_n    = wn * 32 + (lane & 7) + ((lane >> 4) & 1) * 8;
    const int b_koff = ((lane >> 3) & 1) * 8;

    load_chunk(0, 0);

    const int NCHUNK = N_FEAT / 32;    // 16
#pragma unroll 1
    for (int chunk = 0; chunk < NCHUNK; chunk++) {
        const int buf = chunk & 1;
        if (chunk + 1 < NCHUNK) {
            load_chunk(chunk + 1, buf ^ 1);
            cp_wait<1>();
        } else {
            cp_wait<0>();
        }
        __syncthreads();

        const uint32_t Abase = smb + A_BYTE(buf);
        const uint32_t Bbase = smb + B_BYTE(buf);
#pragma unroll
        for (int ks = 0; ks < 2; ks++) {
            const int kb = ks * 16;
            uint32_t a[2][4];
#pragma unroll
            for (int mi = 0; mi < 2; mi++)
                ldsm_x4(a[mi], Abase + (a_row + mi * 16) * AB_STRIDE
                                     + (kb + a_koff) * 2);
            uint32_t b[4][2];
#pragma unroll
            for (int np = 0; np < 2; np++) {
                uint32_t r[4];
                ldsm_x4(r, Bbase + (b_n + np * 16) * AB_STRIDE
                                 + (kb + b_koff) * 2);
                b[np * 2][0]     = r[0];
                b[np * 2][1]     = r[1];
                b[np * 2 + 1][0] = r[2];
                b[np * 2 + 1][1] = r[3];
            }
#pragma unroll
            for (int mi = 0; mi < 2; mi++)
#pragma unroll
                for (int ni = 0; ni < 4; ni++)
                    mma_bf16(acc[mi][ni], a[mi], b[ni]);
        }
        __syncthreads();
    }

    // epilogue: relu -> Hs fp32 (overlays mainloop bufs), then @W2
    float* Hs = smf;   // [128][132]
#pragma unroll
    for (int mi = 0; mi < 2; mi++) {
        int rA = wm * 32 + mi * 16 + (lane >> 2);
#pragma unroll
        for (int ni = 0; ni < 4; ni++) {
            int c0 = wn * 32 + ni * 8 + 2 * (lane & 3);
            Hs[rA * 132 + c0]           = fmaxf(acc[mi][ni][0], 0.0f);
            Hs[rA * 132 + c0 + 1]       = fmaxf(acc[mi][ni][1], 0.0f);
            Hs[(rA + 8) * 132 + c0]     = fmaxf(acc[mi][ni][2], 0.0f);
            Hs[(rA + 8) * 132 + c0 + 1] = fmaxf(acc[mi][ni][3], 0.0f);
        }
    }
    __syncthreads();

    // second layer: 4 threads/row, 4 classes each
    const int r = tid >> 2;          // 0..127
    const int q = tid & 3;           // classes 4q..4q+3
    float o[4] = {0.f, 0.f, 0.f, 0.f};
#pragma unroll 16
    for (int h = 0; h < HIDDEN; h++) {
        float hv = Hs[r * 132 + h];
        float4 w = *(const float4*)&W2s[h * N_CLASS + q * 4];
        o[0] = fmaf(hv, w.x, o[0]); o[1] = fmaf(hv, w.y, o[1]);
        o[2] = fmaf(hv, w.z, o[2]); o[3] = fmaf(hv, w.w, o[3]);
    }
    int gr = r0 + r;
    if (gr < N_NODES) {
        *(float4*)&g_local[(size_t)gr * N_CLASS + q * 4] =
            make_float4(o[0], o[1], o[2], o[3]);
        __half2 h01 = __floats2half2_rn(o[0], o[1]);
        __half2 h23 = __floats2half2_rn(o[2], o[3]);
        ((uint2*)g_loc16)[(size_t)gr * 4 + q] =
            make_uint2(*(uint32_t*)&h01, *(uint32_t*)&h23);
    }
}

// ---------------- propagation: 2 threads/node, fp16 gather, fp32 accum -------
template <int PHASE>
__global__ __launch_bounds__(256)
void prop_kernel(float* __restrict__ dout) {
    const int gt = blockIdx.x * blockDim.x + threadIdx.x;
    const int g  = gt >> 1;
    const int hf = gt & 1;           // classes 8*hf .. 8*hf+7
    if (g >= N_NODES) return;

    const uint4* __restrict__ Lin =
        (PHASE == 0) ? (const uint4*)g_loc16 : (const uint4*)g_buf16;

    const int beg = g_rowptr[g];
    const int end = g_rowptr[g + 1];
    float2 a0 = make_float2(0.f, 0.f), a1 = a0, a2 = a0, a3 = a0;

    int e = beg;
#pragma unroll 1
    for (; e + 8 <= end; e += 8) {
        int d[8];
#pragma unroll
        for (int j = 0; j < 8; j++) d[j] = __ldg(&g_csr[e + j]);
        uint4 t[8];
#pragma unroll
        for (int j = 0; j < 8; j++) t[j] = Lin[(size_t)d[j] * 2 + hf];
#pragma unroll
        for (int j = 0; j < 8; j++) {
            float2 f0 = __half22float2(*(const __half2*)&t[j].x);
            float2 f1 = __half22float2(*(const __half2*)&t[j].y);
            float2 f2 = __half22float2(*(const __half2*)&t[j].z);
            float2 f3 = __half22float2(*(const __half2*)&t[j].w);
            a0.x += f0.x; a0.y += f0.y; a1.x += f1.x; a1.y += f1.y;
            a2.x += f2.x; a2.y += f2.y; a3.x += f3.x; a3.y += f3.y;
        }
    }
    for (; e < end; e++) {
        int d = __ldg(&g_csr[e]);
        uint4 t = Lin[(size_t)d * 2 + hf];
        float2 f0 = __half22float2(*(const __half2*)&t.x);
        float2 f1 = __half22float2(*(const __half2*)&t.y);
        float2 f2 = __half22float2(*(const __half2*)&t.z);
        float2 f3 = __half22float2(*(const __half2*)&t.w);
        a0.x += f0.x; a0.y += f0.y; a1.x += f1.x; a1.y += f1.y;
        a2.x += f2.x; a2.y += f2.y; a3.x += f3.x; a3.y += f3.y;
    }

    const float s = g_scale[g];
    float4 l0 = *(const float4*)&g_local[(size_t)g * N_CLASS + hf * 8];
    float4 l1 = *(const float4*)&g_local[(size_t)g * N_CLASS + hf * 8 + 4];
    float v[8];
    v[0] = s * a0.x + ALPHA * l0.x;  v[1] = s * a0.y + ALPHA * l0.y;
    v[2] = s * a1.x + ALPHA * l0.z;  v[3] = s * a1.y + ALPHA * l0.w;
    v[4] = s * a2.x + ALPHA * l1.x;  v[5] = s * a2.y + ALPHA * l1.y;
    v[6] = s * a3.x + ALPHA * l1.z;  v[7] = s * a3.y + ALPHA * l1.w;

    if (PHASE == 1) {
        float m = v[0];
#pragma unroll
        for (int j = 1; j < 8; j++) m = fmaxf(m, v[j]);
        m = fmaxf(m, __shfl_xor_sync(0xffffffffu, m, 1));
        float sum = 0.0f;
#pragma unroll
        for (int j = 0; j < 8; j++) sum += expf(v[j] - m);
        sum += __shfl_xor_sync(0xffffffffu, sum, 1);
        float ls = m + logf(sum);
        float4 o0 = make_float4(v[0] - ls, v[1] - ls, v[2] - ls, v[3] - ls);
        float4 o1 = make_float4(v[4] - ls, v[5] - ls, v[6] - ls, v[7] - ls);
        *(float4*)&dout[(size_t)g * N_CLASS + hf * 8]     = o0;
        *(float4*)&dout[(size_t)g * N_CLASS + hf * 8 + 4] = o1;
    } else {
        __half2 h01 = __floats2half2_rn(v[0], v[1]);
        __half2 h23 = __floats2half2_rn(v[2], v[3]);
        __half2 h45 = __floats2half2_rn(v[4], v[5]);
        __half2 h67 = __floats2half2_rn(v[6], v[7]);
        uint4 pk = make_uint4(*(uint32_t*)&h01, *(uint32_t*)&h23,
                              *(uint32_t*)&h45, *(uint32_t*)&h67);
        ((uint4*)g_buf16)[(size_t)g * 2 + hf] = pk;
    }
}

// ---------------- launch -----------------------------------------------------
extern "C" void kernel_launch(void* const* d_in, const int* in_sizes, int n_in,
                              void* d_out, int out_size) {
    const float* x   = (const float*)d_in[0];
    const float* W1  = (const float*)d_in[1];
    const float* W2  = (const float*)d_in[2];
    const int*   esr = (const int*)d_in[3];
    const int*   eds = (const int*)d_in[4];
    float*       out = (float*)d_out;

    static cudaStream_t s2 = nullptr;
    static cudaEvent_t evFork = nullptr, evJoin = nullptr;
    static bool init_done = false;
    if (!init_done) {
        cudaStreamCreateWithFlags(&s2, cudaStreamNonBlocking);
        cudaEventCreateWithFlags(&evFork, cudaEventDisableTiming);
        cudaEventCreateWithFlags(&evJoin, cudaEventDisableTiming);
        cudaFuncSetAttribute(gemm_mma_kernel,
                             cudaFuncAttributeMaxDynamicSharedMemorySize,
                             GEMM_SMEM_BYTES);
        init_done = true;
    }

    cudaEventRecord(evFork, 0);
    cudaStreamWaitEvent(s2, evFork, 0);

    zero_deg_kernel<<<256, 256, 0, s2>>>();
    count_deg_kernel<<<2048, 256, 0, s2>>>(esr);
    scan_kernel<<<1, 1024, 0, s2>>>();
    scatter_kernel<<<2048, 256, 0, s2>>>(esr, eds);
    cudaEventRecord(evJoin, s2);

    conv_w1_kernel<<<dim3(4, 16), dim3(32, 8)>>>(W1);
    conv_x_kernel<<<4096, 256>>>(x);
    gemm_mma_kernel<<<(N_NODES + 127) / 128, 512, GEMM_SMEM_BYTES>>>(W2);

    cudaStreamWaitEvent(0, evJoin, 0);

    const int PROP_BLOCKS = (N_NODES * 2 + 255) / 256;
    prop_kernel<0><<<PROP_BLOCKS, 256>>>(nullptr);
    prop_kernel<1><<<PROP_BLOCKS, 256>>>(out);
}